// round 13
// baseline (speedup 1.0000x reference)
#include <cuda_runtime.h>

#define GN    6
#define NN    36
#define NB7   7            // 7x7 counter grid incl. trash row/col
#define NPED  8192
#define HID   128
#define RPB   128          // rows per count block (proven 28 warps/SM config)
#define NSL   16           // j-slices
#define JCH   (NPED / NSL) // 512
#define HB4   (NPED / 4)   // 2048 u32 words per (slice,bin): 4 byte-packed rows/word
#define HB16  (HB4 / 4)    // 512 uint4 per (slice,bin): 16 rows per uint4

// Per-slice byte-packed partial counts, uint4-typed for 16B-aligned wide loads.
// Word layout identical to R12: word w of (sl,c) holds rows 4w..4w+3.
// Fully overwritten by count_kernel every launch -> no zeroing, replay-safe.
__device__ uint4 g8v[NSL * NN * HB16];   // 4.7 MB

// W transposed: WT[c*HID + h] = W[h*NN + c]. Written cooperatively by the 16
// count blocks with blockIdx.x == 0 (disjoint idx ranges); read by embed.
__device__ float g_WT[NN * HID];

// ---------------------------------------------------------------------------
// Phase 1: branch-free occupancy histogram, conflict-free u32 counters.
// Hot loop byte-identical to R8/R12 (measured ~35us, issue-slot floor).
// ---------------------------------------------------------------------------
__global__ __launch_bounds__(RPB) void count_kernel(const float* __restrict__ obs2,
                                                    const float* __restrict__ W) {
    __shared__ unsigned   cnt[NB7 * NB7 * RPB];  // [bin49][t], bank = t%32 (conflict-free)
    __shared__ ulonglong2 pts[JCH / 2];          // 4 KB

    const int t  = threadIdx.x;
    const int i  = blockIdx.x * RPB + t;
    const int j0 = blockIdx.y * JCH;

    // Cooperative W transpose: block (0,sl) handles idx [sl*288, (sl+1)*288).
    if (blockIdx.x == 0) {
        const int base = blockIdx.y * (HID * NN / NSL);
        for (int idx = base + t; idx < base + HID * NN / NSL; idx += RPB) {
            const int h = idx / NN;
            const int c = idx - h * NN;
            g_WT[c * HID + h] = W[idx];
        }
    }

    {
        const ulonglong2* src = (const ulonglong2*)(obs2 + 2 * j0);
#pragma unroll
        for (int k = 0; k < JCH / 2 / RPB; k++)
            pts[t + k * RPB] = src[t + k * RPB];
    }
#pragma unroll
    for (int k = 0; k < NB7 * NB7; k++)
        cnt[k * RPB + t] = 0u;

    const float2 pi = ((const float2*)obs2)[i];
    float nx = -pi.x, ny = -pi.y;
    unsigned long long negpi;
    asm("mov.b64 %0, {%1,%2};" : "=l"(negpi) : "f"(nx), "f"(ny));
    const unsigned long long THREE2 = 0x4040000040400000ULL;  // (3.0f, 3.0f)
    const float MAGIC = 8388608.0f;                           // 2^23

    __syncthreads();

    unsigned* mycnt = cnt + t;

#pragma unroll 4
    for (int k = 0; k < JCH / 2; k++) {
        const ulonglong2 pp = pts[k];   // LDS.128 broadcast: two points
#pragma unroll
        for (int half = 0; half < 2; half++) {
            const unsigned long long pj = half ? pp.y : pp.x;
            unsigned long long d, e;
            // EXACT reference order per lane: rn(pj - pi), then rn(+3)
            asm("add.rn.f32x2 %0, %1, %2;" : "=l"(d) : "l"(pj), "l"(negpi));
            asm("add.rn.f32x2 %0, %1, %2;" : "=l"(e) : "l"(d), "l"(THREE2));
            const float ex = __uint_as_float((unsigned)e);
            const float ey = __uint_as_float((unsigned)(e >> 32));
            float fx, fy;
            asm("add.rm.f32 %0, %1, %2;" : "=f"(fx) : "f"(ex), "f"(MAGIC));
            asm("add.rm.f32 %0, %1, %2;" : "=f"(fy) : "f"(ey), "f"(MAGIC));
            unsigned bx = __float_as_uint(fx) - 0x4B000000u;  // floor; OOR -> huge
            unsigned by = __float_as_uint(fy) - 0x4B000000u;
            bx = umin(bx, 6u);
            by = umin(by, 6u);
            mycnt[(bx * NB7 + by) * RPB] += 1u;  // conflict-free RMW, no branch
        }
    }

    __syncthreads();

    // Flush 36 valid bins, byte-packed 4 rows/word (per-slice counts < 255).
    const int sl = blockIdx.y;
    unsigned* g8 = (unsigned*)g8v;
#pragma unroll
    for (int k = 0; k < 9; k++) {
        const int gidx = k * RPB + t;     // 0..1151
        const int vb   = gidx >> 5;
        const int w    = gidx & 31;
        const int b49  = (vb / GN) * NB7 + (vb % GN);
        const unsigned b0 = cnt[b49 * RPB + 4 * w + 0];
        const unsigned b1 = cnt[b49 * RPB + 4 * w + 1];
        const unsigned b2 = cnt[b49 * RPB + 4 * w + 2];
        const unsigned b3 = cnt[b49 * RPB + 4 * w + 3];
        g8[(sl * NN + vb) * HB4 + blockIdx.x * (RPB / 4) + w] =
            b0 | (b1 << 8) | (b2 << 16) | (b3 << 24);
    }
}

// ---------------------------------------------------------------------------
// Phase 2: reduce slices with WIDE uint4 loads (16 rows per load -> 1
// wavefront per 16B instead of 4 per-word shatters), remove self pair
// (always bin 21), 1-h-per-thread GEMM. 512 blocks x 128 thr = 16 rows.
// ---------------------------------------------------------------------------
__global__ __launch_bounds__(HID) void embed_kernel(const float* __restrict__ b,
                                                    float* __restrict__ out) {
    __shared__ float cs[16][NN];   // reduced counts for this block's 16 rows

    const int t  = threadIdx.x;    // == h
    const int i0 = blockIdx.x * 16;

    // Issue w loads first: lane-consecutive in h -> coalesced; latency
    // overlaps phase A below. WT is L1/L2-resident.
    float w[NN];
#pragma unroll
    for (int c = 0; c < NN; c++)
        w[c] = g_WT[c * HID + t];
    const float bh = b[t];

    // Phase A: one bin per lane (t<36). 16 aligned uint4 loads (one per
    // slice), packed-u16 accumulation (max 960 < 65536).
    if (t < NN) {
        const int c = t;
        const uint4* gp = g8v + c * HB16 + blockIdx.x;
        unsigned a[8];
#pragma unroll
        for (int q = 0; q < 8; q++) a[q] = 0u;
#pragma unroll
        for (int sl = 0; sl < NSL; sl++) {
            const uint4 v = gp[sl * NN * HB16];
            a[0] += __byte_perm(v.x, 0, 0x4140);  // rows 0,1
            a[1] += __byte_perm(v.x, 0, 0x4342);  // rows 2,3
            a[2] += __byte_perm(v.y, 0, 0x4140);  // rows 4,5
            a[3] += __byte_perm(v.y, 0, 0x4342);  // rows 6,7
            a[4] += __byte_perm(v.z, 0, 0x4140);  // rows 8,9
            a[5] += __byte_perm(v.z, 0, 0x4342);  // rows 10,11
            a[6] += __byte_perm(v.w, 0, 0x4140);  // rows 12,13
            a[7] += __byte_perm(v.w, 0, 0x4342);  // rows 14,15
        }
        const unsigned self = (c == 3 * GN + 3) ? 1u : 0u;
#pragma unroll
        for (int q = 0; q < 8; q++) {
            cs[2 * q + 0][c] = (float)((a[q] & 0xFFFFu) - self);
            cs[2 * q + 1][c] = (float)((a[q] >> 16)     - self);
        }
    }
    __syncthreads();

    // Phase B: 16 rows x 36 FMAs; cs reads are warp-uniform broadcasts.
#pragma unroll
    for (int r = 0; r < 16; r++) {
        float acc = bh;
#pragma unroll
        for (int c = 0; c < NN; c++)
            acc = fmaf(cs[r][c], w[c], acc);
        out[(i0 + r) * HID + t] = acc;     // coalesced STG.32
    }
}

// ---------------------------------------------------------------------------
// Inputs: 0 hidden_state (unused), 1 obs1 (unused), 2 obs2 [8192,2],
// 3 W [128,36], 4 b [128]. Output fp32 [8192,128].
// ---------------------------------------------------------------------------
extern "C" void kernel_launch(void* const* d_in, const int* in_sizes, int n_in,
                              void* d_out, int out_size) {
    const float* obs2 = (const float*)d_in[2];
    const float* W    = (const float*)d_in[3];
    const float* b    = (const float*)d_in[4];
    float*       out  = (float*)d_out;

    dim3 g1(NPED / RPB, NSL);        // 64 x 16 = 1024 blocks
    count_kernel<<<g1, RPB>>>(obs2, W);
    embed_kernel<<<NPED / 16, HID>>>(b, out);
}